// round 13
// baseline (speedup 1.0000x reference)
#include <cuda_runtime.h>
#include <cuda_bf16.h>
#include <cstdint>

#define N_NODES 40000
#define N_EDGES 640000
#define CH 128
#define NCLS 40
#define CAP 96          // bucket capacity per node (mean degree 16, Poisson tail ~0)

// ---- scratch (static __device__ arrays; no allocations allowed) ----
__device__ float4 g_b0[N_NODES * 32];
__device__ float4 g_b1[N_NODES * 32];
__device__ float4 g_b2[N_NODES * 32];
__device__ int    g_cursor[N_NODES];
__device__ int    g_bsrcs[N_NODES * CAP];   // bucketed src lists
__device__ int    g_is64;

__device__ __forceinline__ float4* pick_buf(int s) {
    return (s == 0) ? g_b0 : (s == 1) ? g_b1 : g_b2;
}

__device__ __forceinline__ uint32_t smem_u32(const void* p) {
    uint32_t a;
    asm("{ .reg .u64 t; cvta.to.shared.u64 t, %1; cvt.u32.u64 %0, t; }" : "=r"(a) : "l"(p));
    return a;
}

// ---- width-aware edge-index load (dtype detected in k_init) ----
__device__ __forceinline__ int ld_idx(const int* __restrict__ e, int pos) {
    int v = g_is64 ? e[2 * pos] : e[pos];
    return min(max(v, 0), N_NODES - 1);
}

// ================== bucket CSR build (2 kernels) ==================
__global__ void k_init(const int* __restrict__ e) {
    int i = blockIdx.x * blockDim.x + threadIdx.x;
    if (i < N_NODES) g_cursor[i] = 0;
    if (i == 0) {
        int nz = 0;
        for (int j = 1; j < 256; j += 2) nz |= e[j];
        g_is64 = (nz == 0) ? 1 : 0;
    }
}
__global__ void k_scatter(const int* __restrict__ e) {
    int i = blockIdx.x * blockDim.x + threadIdx.x;
    if (i < N_EDGES) {
        int d = ld_idx(e, N_EDGES + i);
        int p = atomicAdd(&g_cursor[d], 1);
        if (p < CAP) g_bsrcs[d * CAP + p] = ld_idx(e, i);
    }
}

// ========== aggregation: dst[n] = X[n] + sum_{e: dst=n} X[src[e]] ==========
__global__ void k_agg(const float4* __restrict__ Xext, int src_sel, int dst_sel) {
    int warp = (blockIdx.x * blockDim.x + threadIdx.x) >> 5;
    int lane = threadIdx.x & 31;
    if (warp >= N_NODES) return;
    const float4* X4 = (src_sel < 0) ? Xext : pick_buf(src_sel);
    float4 acc = X4[warp * 32 + lane];
    float4 acc2 = make_float4(0.f, 0.f, 0.f, 0.f);
    int n  = min(g_cursor[warp], CAP);
    const int* srcs = &g_bsrcs[warp * CAP];
    int j = 0;
    for (; j + 1 < n; j += 2) {
        int sA = srcs[j];
        int sB = srcs[j + 1];
        float4 vA = X4[sA * 32 + lane];
        float4 vB = X4[sB * 32 + lane];
        acc.x  += vA.x; acc.y  += vA.y; acc.z  += vA.z; acc.w  += vA.w;
        acc2.x += vB.x; acc2.y += vB.y; acc2.z += vB.z; acc2.w += vB.w;
    }
    if (j < n) {
        int s = srcs[j];
        float4 v = X4[s * 32 + lane];
        acc.x += v.x; acc.y += v.y; acc.z += v.z; acc.w += v.w;
    }
    acc.x += acc2.x; acc.y += acc2.y; acc.z += acc2.z; acc.w += acc2.w;
    pick_buf(dst_sel)[warp * 32 + lane] = acc;
}

// ======================= MMA primitives =======================
#define LDA 136   // bf16 per smem row (128 + 8 pad) -> 272B stride

__device__ __forceinline__ uint32_t pack_bf2(__nv_bfloat16 a, __nv_bfloat16 b) {
    __nv_bfloat162 p(a, b);
    return *(uint32_t*)&p;
}
__device__ __forceinline__ uint32_t split_pack_hi(float a, float b,
                                                  uint32_t& lo_out) {
    __nv_bfloat16 ha = __float2bfloat16(a), hb = __float2bfloat16(b);
    lo_out = pack_bf2(__float2bfloat16(a - __bfloat162float(ha)),
                      __float2bfloat16(b - __bfloat162float(hb)));
    return pack_bf2(ha, hb);
}
__device__ __forceinline__ void ldm_x4(uint32_t* r, uint32_t addr) {
    asm volatile("ldmatrix.sync.aligned.m8n8.x4.shared.b16 {%0,%1,%2,%3}, [%4];"
        : "=r"(r[0]), "=r"(r[1]), "=r"(r[2]), "=r"(r[3]) : "r"(addr));
}
__device__ __forceinline__ void mma_bf16(float* c, const uint32_t* a, const uint32_t* b) {
    asm volatile(
        "mma.sync.aligned.m16n8k16.row.col.f32.bf16.bf16.f32 "
        "{%0,%1,%2,%3}, {%4,%5,%6,%7}, {%8,%9}, {%0,%1,%2,%3};"
        : "+f"(c[0]), "+f"(c[1]), "+f"(c[2]), "+f"(c[3])
        : "r"(a[0]), "r"(a[1]), "r"(a[2]), "r"(a[3]), "r"(b[0]), "r"(b[1]));
}

// 128xBNx128 3-product mainloop; B fragments loaded pairwise via ldmatrix.x4
template<int NI>
__device__ __forceinline__ void gemm_mainloop(
    uint32_t sAh, uint32_t sAl, uint32_t sBh, uint32_t sBl,
    int wm, int wn, int lane, float acc[2][NI][4]) {
    const int la  = lane & 15;
    const int lka = (lane >> 4) * 8;
    const int lbx = ((lane >> 4) & 1) * 8 + (lane & 7);   // row for paired-B x4
    const int lkb = ((lane >> 3) & 1) * 8;
#pragma unroll
    for (int kb = 0; kb < 8; kb++) {
        uint32_t ah[2][4], al[2][4], bh[NI][2], bl[NI][2];
#pragma unroll
        for (int mi = 0; mi < 2; mi++) {
            uint32_t off = ((wm + mi * 16 + la) * LDA + kb * 16 + lka) * 2;
            ldm_x4(ah[mi], sAh + off);
            ldm_x4(al[mi], sAl + off);
        }
#pragma unroll
        for (int np = 0; np < NI; np += 2) {   // 2 n-frags per x4
            uint32_t off = ((wn + np * 8 + lbx) * LDA + kb * 16 + lkb) * 2;
            uint32_t t4[4];
            ldm_x4(t4, sBh + off);
            bh[np][0] = t4[0]; bh[np][1] = t4[1];
            bh[np + 1][0] = t4[2]; bh[np + 1][1] = t4[3];
            ldm_x4(t4, sBl + off);
            bl[np][0] = t4[0]; bl[np][1] = t4[1];
            bl[np + 1][0] = t4[2]; bl[np + 1][1] = t4[3];
        }
#pragma unroll
        for (int mi = 0; mi < 2; mi++)
#pragma unroll
            for (int ni = 0; ni < NI; ni++) {
                mma_bf16(acc[mi][ni], ah[mi], bh[ni]);
                mma_bf16(acc[mi][ni], ah[mi], bl[ni]);
                mma_bf16(acc[mi][ni], al[mi], bh[ni]);
            }
    }
}

// fp32 weight [128][128] (k-major) -> [n][k] bf16 hi/lo smem tiles
__device__ __forceinline__ void load_weights(
    const float* __restrict__ W, __nv_bfloat16* Bh, __nv_bfloat16* Bl, int tid) {
#pragma unroll
    for (int it = 0; it < 8; it++) {
        int idx = tid + it * 512;
        int n  = idx & 127;
        int k4 = idx >> 7;
        float f[4];
#pragma unroll
        for (int j = 0; j < 4; j++) f[j] = W[(k4 * 4 + j) * 128 + n];
        uint2 uh, ul;
        uh.x = split_pack_hi(f[0], f[1], ul.x);
        uh.y = split_pack_hi(f[2], f[3], ul.y);
        int off = n * LDA + k4 * 4;
        *(uint2*)&Bh[off] = uh;
        *(uint2*)&Bl[off] = ul;
    }
}

#define GEMM_BLOCKS ((N_NODES + 127) / 128)   // 313
#define MLP_GRID 296   // 1-2 tiles per CTA; two 1-CTA/SM waves beat the 3-tile tail

// ========== fused MLP (persistent): out = relu( relu(A@Wa+ba) @ Wb + bb ) ==========
__global__ __launch_bounds__(512, 1)
void k_mlp(int src_sel,
           const float* __restrict__ Wa, const float* __restrict__ ba,
           const float* __restrict__ Wb, const float* __restrict__ bb,
           int dst_sel) {
    extern __shared__ char sm[];
    constexpr int SZ = 128 * LDA * 2;          // 34816 B
    const int OFF_AH = 1024,        OFF_AL = OFF_AH + SZ;
    const int OFF_BHA = OFF_AL + SZ,  OFF_BLA = OFF_BHA + SZ;
    const int OFF_BHB = OFF_BLA + SZ, OFF_BLB = OFF_BHB + SZ;
    float* sbA = (float*)sm;
    float* sbB = (float*)(sm + 512);
    __nv_bfloat16* Ah  = (__nv_bfloat16*)(sm + OFF_AH);
    __nv_bfloat16* Al  = (__nv_bfloat16*)(sm + OFF_AL);
    __nv_bfloat16* BhA = (__nv_bfloat16*)(sm + OFF_BHA);
    __nv_bfloat16* BlA = (__nv_bfloat16*)(sm + OFF_BLA);
    __nv_bfloat16* BhB = (__nv_bfloat16*)(sm + OFF_BHB);
    __nv_bfloat16* BlB = (__nv_bfloat16*)(sm + OFF_BLB);

    const int tid = threadIdx.x, lane = tid & 31, wid = tid >> 5;
    if (tid < 128) { sbA[tid] = ba[tid]; sbB[tid] = bb[tid]; }
    load_weights(Wa, BhA, BlA, tid);
    load_weights(Wb, BhB, BlB, tid);

    const int wm = (wid >> 2) * 32;
    const int wn = (wid & 3) * 32;
    const uint32_t sAh = smem_u32(Ah), sAl = smem_u32(Al);
    const float4* A4 = pick_buf(src_sel);
    float* C = (float*)pick_buf(dst_sel);

    for (int t = blockIdx.x; t < GEMM_BLOCKS; t += MLP_GRID) {
        const int m0 = t * 128;
        __syncthreads();   // prev iter's mainloop2 reads of A done; iter0: weights visible

        // ---- A tile: fp32 -> hi/lo bf16 split ----
#pragma unroll
        for (int it = 0; it < 8; it++) {
            int idx = tid + it * 512;
            int r  = idx >> 5;
            int kk = idx & 31;
            int row = m0 + r;
            float4 v = make_float4(0.f, 0.f, 0.f, 0.f);
            if (row < N_NODES) v = A4[row * 32 + kk];
            uint2 uh, ul;
            uh.x = split_pack_hi(v.x, v.y, ul.x);
            uh.y = split_pack_hi(v.z, v.w, ul.y);
            int off = r * LDA + kk * 4;
            *(uint2*)&Ah[off] = uh;
            *(uint2*)&Al[off] = ul;
        }
        __syncthreads();

        // ---- phase 1: h = relu(A @ Wa + ba), re-packed into A tiles ----
        float acc[2][4][4];
#pragma unroll
        for (int i = 0; i < 2; i++)
#pragma unroll
            for (int j = 0; j < 4; j++)
#pragma unroll
                for (int q = 0; q < 4; q++) acc[i][j][q] = 0.f;

        gemm_mainloop<4>(sAh, sAl, smem_u32(BhA), smem_u32(BlA), wm, wn, lane, acc);
        __syncthreads();                        // all reads of A tiles done

#pragma unroll
        for (int mi = 0; mi < 2; mi++) {
            int r_lo = wm + mi * 16 + (lane >> 2);
            int r_hi = r_lo + 8;
#pragma unroll
            for (int ni = 0; ni < 4; ni++) {
                int col = wn + ni * 8 + (lane & 3) * 2;
                float v00 = fmaxf(acc[mi][ni][0] + sbA[col], 0.f);
                float v01 = fmaxf(acc[mi][ni][1] + sbA[col + 1], 0.f);
                float v10 = fmaxf(acc[mi][ni][2] + sbA[col], 0.f);
                float v11 = fmaxf(acc[mi][ni][3] + sbA[col + 1], 0.f);
                uint32_t lo;
                *(uint32_t*)&Ah[r_lo * LDA + col] = split_pack_hi(v00, v01, lo);
                *(uint32_t*)&Al[r_lo * LDA + col] = lo;
                *(uint32_t*)&Ah[r_hi * LDA + col] = split_pack_hi(v10, v11, lo);
                *(uint32_t*)&Al[r_hi * LDA + col] = lo;
            }
        }
        __syncthreads();                        // h tiles complete

        // ---- phase 2: out = relu(h @ Wb + bb) ----
#pragma unroll
        for (int i = 0; i < 2; i++)
#pragma unroll
            for (int j = 0; j < 4; j++)
#pragma unroll
                for (int q = 0; q < 4; q++) acc[i][j][q] = 0.f;

        gemm_mainloop<4>(sAh, sAl, smem_u32(BhB), smem_u32(BlB), wm, wn, lane, acc);

#pragma unroll
        for (int mi = 0; mi < 2; mi++) {
            int r_lo = m0 + wm + mi * 16 + (lane >> 2);
            int r_hi = r_lo + 8;
#pragma unroll
            for (int ni = 0; ni < 4; ni++) {
                int col = wn + ni * 8 + (lane & 3) * 2;
                float v00 = fmaxf(acc[mi][ni][0] + sbB[col], 0.f);
                float v01 = fmaxf(acc[mi][ni][1] + sbB[col + 1], 0.f);
                float v10 = fmaxf(acc[mi][ni][2] + sbB[col], 0.f);
                float v11 = fmaxf(acc[mi][ni][3] + sbB[col + 1], 0.f);
                if (r_lo < N_NODES) *(float2*)&C[r_lo * 128 + col] = make_float2(v00, v01);
                if (r_hi < N_NODES) *(float2*)&C[r_hi * 128 + col] = make_float2(v10, v11);
            }
        }
    }
}

// ========== classifier GEMM (BN=64, N padded from 40) ==========
__global__ __launch_bounds__(512, 1)
void k_cls(int src_sel, const float* __restrict__ W,
           const float* __restrict__ bias, float* __restrict__ Cext, int ncols) {
    extern __shared__ char sm[];
    constexpr int SZA = 128 * LDA * 2;
    constexpr int SZB = 64 * LDA * 2;
    const int OFF_AH = 512, OFF_AL = OFF_AH + SZA;
    const int OFF_BH = OFF_AL + SZA, OFF_BL = OFF_BH + SZB;
    float* sbias = (float*)sm;
    __nv_bfloat16* Ah = (__nv_bfloat16*)(sm + OFF_AH);
    __nv_bfloat16* Al = (__nv_bfloat16*)(sm + OFF_AL);
    __nv_bfloat16* Bh = (__nv_bfloat16*)(sm + OFF_BH);
    __nv_bfloat16* Bl = (__nv_bfloat16*)(sm + OFF_BL);

    const int tid = threadIdx.x, lane = tid & 31, wid = tid >> 5;
    const int m0 = blockIdx.x * 128;
    if (tid < 64) sbias[tid] = (tid < ncols) ? bias[tid] : 0.f;

    const float4* A4 = pick_buf(src_sel);
#pragma unroll
    for (int it = 0; it < 8; it++) {
        int idx = tid + it * 512;
        int r  = idx >> 5;
        int kk = idx & 31;
        int row = m0 + r;
        float4 v = make_float4(0.f, 0.f, 0.f, 0.f);
        if (row < N_NODES) v = A4[row * 32 + kk];
        uint2 uh, ul;
        uh.x = split_pack_hi(v.x, v.y, ul.x);
        uh.y = split_pack_hi(v.z, v.w, ul.y);
        int off = r * LDA + kk * 4;
        *(uint2*)&Ah[off] = uh;
        *(uint2*)&Al[off] = ul;
    }
#pragma unroll
    for (int it = 0; it < 4; it++) {
        int idx = tid + it * 512;
        int n  = idx & 63;
        int k4 = idx >> 6;
        float f[4];
#pragma unroll
        for (int j = 0; j < 4; j++)
            f[j] = (n < ncols) ? W[(k4 * 4 + j) * ncols + n] : 0.f;
        uint2 uh, ul;
        uh.x = split_pack_hi(f[0], f[1], ul.x);
        uh.y = split_pack_hi(f[2], f[3], ul.y);
        int off = n * LDA + k4 * 4;
        *(uint2*)&Bh[off] = uh;
        *(uint2*)&Bl[off] = ul;
    }
    __syncthreads();

    const int wm = (wid >> 2) * 32;
    const int wn = (wid & 3) * 16;
    float acc[2][2][4];
#pragma unroll
    for (int i = 0; i < 2; i++)
#pragma unroll
        for (int j = 0; j < 2; j++)
#pragma unroll
            for (int q = 0; q < 4; q++) acc[i][j][q] = 0.f;

    gemm_mainloop<2>(smem_u32(Ah), smem_u32(Al), smem_u32(Bh), smem_u32(Bl),
                     wm, wn, lane, acc);

#pragma unroll
    for (int mi = 0; mi < 2; mi++) {
        int r_lo = m0 + wm + mi * 16 + (lane >> 2);
        int r_hi = r_lo + 8;
#pragma unroll
        for (int ni = 0; ni < 2; ni++) {
            int col = wn + ni * 8 + (lane & 3) * 2;
            float v00 = acc[mi][ni][0] + sbias[col];
            float v01 = acc[mi][ni][1] + sbias[col + 1];
            float v10 = acc[mi][ni][2] + sbias[col];
            float v11 = acc[mi][ni][3] + sbias[col + 1];
            if (r_lo < N_NODES) {
                if (col < ncols)     Cext[r_lo * ncols + col]     = v00;
                if (col + 1 < ncols) Cext[r_lo * ncols + col + 1] = v01;
            }
            if (r_hi < N_NODES) {
                if (col < ncols)     Cext[r_hi * ncols + col]     = v10;
                if (col + 1 < ncols) Cext[r_hi * ncols + col + 1] = v11;
            }
        }
    }
}

// ============================ launch ============================
extern "C" void kernel_launch(void* const* d_in, const int* in_sizes, int n_in,
                              void* d_out, int out_size) {
    const float4* x  = (const float4*)d_in[0];
    const int*    ei = (const int*)d_in[1];
    const float* w1a = (const float*)d_in[2];
    const float* b1a = (const float*)d_in[3];
    const float* w1b = (const float*)d_in[4];
    const float* b1b = (const float*)d_in[5];
    const float* w2a = (const float*)d_in[6];
    const float* b2a = (const float*)d_in[7];
    const float* w2b = (const float*)d_in[8];
    const float* b2b = (const float*)d_in[9];
    const float* wlin = (const float*)d_in[10];
    const float* blin = (const float*)d_in[11];
    float* out = (float*)d_out;

    const int SMEM_M = 1024 + 6 * (128 * LDA * 2);                       // 209920
    const int SMEM_C = 512 + 2 * (128 * LDA * 2) + 2 * (64 * LDA * 2);   // 104960
    cudaFuncSetAttribute(k_mlp, cudaFuncAttributeMaxDynamicSharedMemorySize, SMEM_M);
    cudaFuncSetAttribute(k_cls, cudaFuncAttributeMaxDynamicSharedMemorySize, SMEM_C);

    const int EDGE_BLOCKS = (N_EDGES + 255) / 256;       // 2500
    const int NODE_BLOCKS = (N_NODES + 255) / 256;       // 157
    const int AGG_BLOCKS  = (N_NODES * 32 + 255) / 256;  // 5000

    // bucket CSR build (2 kernels)
    k_init<<<NODE_BLOCKS, 256>>>(ei);
    k_scatter<<<EDGE_BLOCKS, 256>>>(ei);

    // layer 1: agg (x -> b0), fused persistent MLP (b0 -> b1)
    k_agg<<<AGG_BLOCKS, 256>>>(x, -1, 0);
    k_mlp<<<MLP_GRID, 512, SMEM_M>>>(0, w1a, b1a, w1b, b1b, 1);

    // layer 2: agg (b1 -> b0), fused persistent MLP (b0 -> b2)
    k_agg<<<AGG_BLOCKS, 256>>>(nullptr, 1, 0);
    k_mlp<<<MLP_GRID, 512, SMEM_M>>>(0, w2a, b2a, w2b, b2b, 2);

    // classifier: out = b2 @ wlin + blin
    k_cls<<<GEMM_BLOCKS, 512, SMEM_C>>>(2, wlin, blin, out, NCLS);
}

// round 14
// speedup vs baseline: 1.0551x; 1.0551x over previous
#include <cuda_runtime.h>
#include <cuda_bf16.h>
#include <cstdint>

#define N_NODES 40000
#define N_EDGES 640000
#define CH 128
#define NCLS 40
#define CAP 96          // bucket capacity per node (mean degree 16, Poisson tail ~0)

// ---- scratch (static __device__ arrays; no allocations allowed) ----
__device__ float4 g_b0[N_NODES * 32];
__device__ float4 g_b1[N_NODES * 32];
__device__ float4 g_b2[N_NODES * 32];
__device__ int    g_cursor[N_NODES];
__device__ int    g_bsrcs[N_NODES * CAP];   // bucketed src lists
__device__ int    g_is64;

__device__ __forceinline__ float4* pick_buf(int s) {
    return (s == 0) ? g_b0 : (s == 1) ? g_b1 : g_b2;
}

__device__ __forceinline__ uint32_t smem_u32(const void* p) {
    uint32_t a;
    asm("{ .reg .u64 t; cvta.to.shared.u64 t, %1; cvt.u32.u64 %0, t; }" : "=r"(a) : "l"(p));
    return a;
}

// ---- width-aware edge-index load (dtype detected in k_init) ----
__device__ __forceinline__ int ld_idx(const int* __restrict__ e, int pos) {
    int v = g_is64 ? e[2 * pos] : e[pos];
    return min(max(v, 0), N_NODES - 1);
}

// ================== bucket CSR build (2 kernels) ==================
__global__ void k_init(const int* __restrict__ e) {
    int i = blockIdx.x * blockDim.x + threadIdx.x;
    if (i < N_NODES) g_cursor[i] = 0;
    if (i == 0) {
        int nz = 0;
        for (int j = 1; j < 256; j += 2) nz |= e[j];
        g_is64 = (nz == 0) ? 1 : 0;
    }
}
__global__ void k_scatter(const int* __restrict__ e) {
    int i = blockIdx.x * blockDim.x + threadIdx.x;
    if (i < N_EDGES) {
        int d = ld_idx(e, N_EDGES + i);
        int p = atomicAdd(&g_cursor[d], 1);
        if (p < CAP) g_bsrcs[d * CAP + p] = ld_idx(e, i);
    }
}

// ========== aggregation: dst[n] = X[n] + sum_{e: dst=n} X[src[e]] ==========
// warp-per-node, 4-way ILP on the random row gathers.
__global__ void k_agg(const float4* __restrict__ Xext, int src_sel, int dst_sel) {
    int warp = (blockIdx.x * blockDim.x + threadIdx.x) >> 5;
    int lane = threadIdx.x & 31;
    if (warp >= N_NODES) return;
    const float4* X4 = (src_sel < 0) ? Xext : pick_buf(src_sel);
    float4 a0 = X4[warp * 32 + lane];
    float4 a1 = make_float4(0.f, 0.f, 0.f, 0.f);
    float4 a2 = a1, a3 = a1;
    int n  = min(g_cursor[warp], CAP);
    const int* srcs = &g_bsrcs[warp * CAP];
    int j = 0;
    for (; j + 3 < n; j += 4) {
        int sA = srcs[j],     sB = srcs[j + 1];
        int sC = srcs[j + 2], sD = srcs[j + 3];
        float4 vA = X4[sA * 32 + lane], vB = X4[sB * 32 + lane];
        float4 vC = X4[sC * 32 + lane], vD = X4[sD * 32 + lane];
        a0.x += vA.x; a0.y += vA.y; a0.z += vA.z; a0.w += vA.w;
        a1.x += vB.x; a1.y += vB.y; a1.z += vB.z; a1.w += vB.w;
        a2.x += vC.x; a2.y += vC.y; a2.z += vC.z; a2.w += vC.w;
        a3.x += vD.x; a3.y += vD.y; a3.z += vD.z; a3.w += vD.w;
    }
    for (; j < n; j++) {
        int s = srcs[j];
        float4 v = X4[s * 32 + lane];
        a0.x += v.x; a0.y += v.y; a0.z += v.z; a0.w += v.w;
    }
    a0.x += a1.x + a2.x + a3.x; a0.y += a1.y + a2.y + a3.y;
    a0.z += a1.z + a2.z + a3.z; a0.w += a1.w + a2.w + a3.w;
    pick_buf(dst_sel)[warp * 32 + lane] = a0;
}

// ======================= MMA primitives =======================
#define LDA 136   // bf16 per smem row (128 + 8 pad) -> 272B stride (17x16B: conflict-free)

__device__ __forceinline__ uint32_t pack_bf2(__nv_bfloat16 a, __nv_bfloat16 b) {
    __nv_bfloat162 p(a, b);
    return *(uint32_t*)&p;
}
__device__ __forceinline__ uint32_t split_pack_hi(float a, float b,
                                                  uint32_t& lo_out) {
    __nv_bfloat16 ha = __float2bfloat16(a), hb = __float2bfloat16(b);
    lo_out = pack_bf2(__float2bfloat16(a - __bfloat162float(ha)),
                      __float2bfloat16(b - __bfloat162float(hb)));
    return pack_bf2(ha, hb);
}
__device__ __forceinline__ void ldm_x4(uint32_t* r, uint32_t addr) {
    asm volatile("ldmatrix.sync.aligned.m8n8.x4.shared.b16 {%0,%1,%2,%3}, [%4];"
        : "=r"(r[0]), "=r"(r[1]), "=r"(r[2]), "=r"(r[3]) : "r"(addr));
}
__device__ __forceinline__ void mma_bf16(float* c, const uint32_t* a, const uint32_t* b) {
    asm volatile(
        "mma.sync.aligned.m16n8k16.row.col.f32.bf16.bf16.f32 "
        "{%0,%1,%2,%3}, {%4,%5,%6,%7}, {%8,%9}, {%0,%1,%2,%3};"
        : "+f"(c[0]), "+f"(c[1]), "+f"(c[2]), "+f"(c[3])
        : "r"(a[0]), "r"(a[1]), "r"(a[2]), "r"(a[3]), "r"(b[0]), "r"(b[1]));
}

// 128xBNx128 3-product mainloop; B fragments loaded pairwise via ldmatrix.x4
template<int NI>
__device__ __forceinline__ void gemm_mainloop(
    uint32_t sAh, uint32_t sAl, uint32_t sBh, uint32_t sBl,
    int wm, int wn, int lane, float acc[2][NI][4]) {
    const int la  = lane & 15;
    const int lka = (lane >> 4) * 8;
    const int lbx = ((lane >> 4) & 1) * 8 + (lane & 7);   // row for paired-B x4
    const int lkb = ((lane >> 3) & 1) * 8;
#pragma unroll
    for (int kb = 0; kb < 8; kb++) {
        uint32_t ah[2][4], al[2][4], bh[NI][2], bl[NI][2];
#pragma unroll
        for (int mi = 0; mi < 2; mi++) {
            uint32_t off = ((wm + mi * 16 + la) * LDA + kb * 16 + lka) * 2;
            ldm_x4(ah[mi], sAh + off);
            ldm_x4(al[mi], sAl + off);
        }
#pragma unroll
        for (int np = 0; np < NI; np += 2) {   // 2 n-frags per x4
            uint32_t off = ((wn + np * 8 + lbx) * LDA + kb * 16 + lkb) * 2;
            uint32_t t4[4];
            ldm_x4(t4, sBh + off);
            bh[np][0] = t4[0]; bh[np][1] = t4[1];
            bh[np + 1][0] = t4[2]; bh[np + 1][1] = t4[3];
            ldm_x4(t4, sBl + off);
            bl[np][0] = t4[0]; bl[np][1] = t4[1];
            bl[np + 1][0] = t4[2]; bl[np + 1][1] = t4[3];
        }
#pragma unroll
        for (int mi = 0; mi < 2; mi++)
#pragma unroll
            for (int ni = 0; ni < NI; ni++) {
                mma_bf16(acc[mi][ni], ah[mi], bh[ni]);
                mma_bf16(acc[mi][ni], ah[mi], bl[ni]);
                mma_bf16(acc[mi][ni], al[mi], bh[ni]);
            }
    }
}

// fp32 weight [128][128] (k-major) -> [n][k] bf16 hi/lo smem tiles
__device__ __forceinline__ void load_weights(
    const float* __restrict__ W, __nv_bfloat16* Bh, __nv_bfloat16* Bl, int tid) {
#pragma unroll
    for (int it = 0; it < 8; it++) {
        int idx = tid + it * 512;
        int n  = idx & 127;
        int k4 = idx >> 7;
        float f[4];
#pragma unroll
        for (int j = 0; j < 4; j++) f[j] = W[(k4 * 4 + j) * 128 + n];
        uint2 uh, ul;
        uh.x = split_pack_hi(f[0], f[1], ul.x);
        uh.y = split_pack_hi(f[2], f[3], ul.y);
        int off = n * LDA + k4 * 4;
        *(uint2*)&Bh[off] = uh;
        *(uint2*)&Bl[off] = ul;
    }
}

#define GEMM_BLOCKS ((N_NODES + 127) / 128)   // 313
#define MLP_GRID 148                          // persistent: one CTA per SM

// ========== fused MLP (persistent), optionally + classifier ==========
// DO_CLS=0: dst = relu( relu(A@Wa+ba) @ Wb + bb )   -> pick_buf(dst_sel)
// DO_CLS=1: out = ( relu( relu(A@Wa+ba) @ Wb + bb ) ) @ Wc + bc  -> Cout [N,NCLS]
//   h2 never touches global; Wc lives in the Wa tile slots after mainloop1.
template<int DO_CLS>
__global__ __launch_bounds__(512, 1)
void k_mlp(int src_sel,
           const float* __restrict__ Wa, const float* __restrict__ ba,
           const float* __restrict__ Wb, const float* __restrict__ bb,
           int dst_sel,
           const float* __restrict__ Wc, const float* __restrict__ bc,
           float* __restrict__ Cout) {
    extern __shared__ char sm[];
    constexpr int SZ = 128 * LDA * 2;          // 34816 B
    const int OFF_AH = 2048,        OFF_AL = OFF_AH + SZ;
    const int OFF_BHA = OFF_AL + SZ,  OFF_BLA = OFF_BHA + SZ;
    const int OFF_BHB = OFF_BLA + SZ, OFF_BLB = OFF_BHB + SZ;
    float* sbA = (float*)sm;                    // [0,512)
    float* sbB = (float*)(sm + 512);            // [512,1024)
    float* sbC = (float*)(sm + 1024);           // [1024,1280) 64 floats
    __nv_bfloat16* Ah  = (__nv_bfloat16*)(sm + OFF_AH);
    __nv_bfloat16* Al  = (__nv_bfloat16*)(sm + OFF_AL);
    __nv_bfloat16* BhA = (__nv_bfloat16*)(sm + OFF_BHA);
    __nv_bfloat16* BlA = (__nv_bfloat16*)(sm + OFF_BLA);
    __nv_bfloat16* BhB = (__nv_bfloat16*)(sm + OFF_BHB);
    __nv_bfloat16* BlB = (__nv_bfloat16*)(sm + OFF_BLB);

    const int tid = threadIdx.x, lane = tid & 31, wid = tid >> 5;
    if (tid < 128) { sbA[tid] = ba[tid]; sbB[tid] = bb[tid]; }
    if (DO_CLS && tid < 64) sbC[tid] = (tid < NCLS) ? bc[tid] : 0.f;
    if (!DO_CLS) load_weights(Wa, BhA, BlA, tid);   // CLS path reloads Wa per tile
    load_weights(Wb, BhB, BlB, tid);

    const int wm = (wid >> 2) * 32;
    const int wn = (wid & 3) * 32;
    const uint32_t sAh = smem_u32(Ah), sAl = smem_u32(Al);
    const float4* A4 = pick_buf(src_sel);
    float* C = (float*)pick_buf(dst_sel);

    for (int t = blockIdx.x; t < GEMM_BLOCKS; t += MLP_GRID) {
        const int m0 = t * 128;
        __syncthreads();   // prev iter's last mainloop reads done; iter0: weights visible

        if (DO_CLS) load_weights(Wa, BhA, BlA, tid);   // Wa slot was Wc last iter

        // ---- A tile: fp32 -> hi/lo bf16 split ----
#pragma unroll
        for (int it = 0; it < 8; it++) {
            int idx = tid + it * 512;
            int r  = idx >> 5;
            int kk = idx & 31;
            int row = m0 + r;
            float4 v = make_float4(0.f, 0.f, 0.f, 0.f);
            if (row < N_NODES) v = A4[row * 32 + kk];
            uint2 uh, ul;
            uh.x = split_pack_hi(v.x, v.y, ul.x);
            uh.y = split_pack_hi(v.z, v.w, ul.y);
            int off = r * LDA + kk * 4;
            *(uint2*)&Ah[off] = uh;
            *(uint2*)&Al[off] = ul;
        }
        __syncthreads();

        // ---- phase 1: h = relu(A @ Wa + ba) ----
        float acc[2][4][4];
#pragma unroll
        for (int i = 0; i < 2; i++)
#pragma unroll
            for (int j = 0; j < 4; j++)
#pragma unroll
                for (int q = 0; q < 4; q++) acc[i][j][q] = 0.f;

        gemm_mainloop<4>(sAh, sAl, smem_u32(BhA), smem_u32(BlA), wm, wn, lane, acc);
        __syncthreads();                        // all reads of A (and Wa) done

        // repack h into A tiles; CLS: also stage Wc into the free Wa slots
#pragma unroll
        for (int mi = 0; mi < 2; mi++) {
            int r_lo = wm + mi * 16 + (lane >> 2);
            int r_hi = r_lo + 8;
#pragma unroll
            for (int ni = 0; ni < 4; ni++) {
                int col = wn + ni * 8 + (lane & 3) * 2;
                float v00 = fmaxf(acc[mi][ni][0] + sbA[col], 0.f);
                float v01 = fmaxf(acc[mi][ni][1] + sbA[col + 1], 0.f);
                float v10 = fmaxf(acc[mi][ni][2] + sbA[col], 0.f);
                float v11 = fmaxf(acc[mi][ni][3] + sbA[col + 1], 0.f);
                uint32_t lo;
                *(uint32_t*)&Ah[r_lo * LDA + col] = split_pack_hi(v00, v01, lo);
                *(uint32_t*)&Al[r_lo * LDA + col] = lo;
                *(uint32_t*)&Ah[r_hi * LDA + col] = split_pack_hi(v10, v11, lo);
                *(uint32_t*)&Al[r_hi * LDA + col] = lo;
            }
        }
        if (DO_CLS) {
#pragma unroll
            for (int it = 0; it < 4; it++) {
                int idx = tid + it * 512;      // 2048 (n,k4) pairs: 64 x 32
                int n  = idx & 63;
                int k4 = idx >> 6;
                float f[4];
#pragma unroll
                for (int j = 0; j < 4; j++)
                    f[j] = (n < NCLS) ? Wc[(k4 * 4 + j) * NCLS + n] : 0.f;
                uint2 uh, ul;
                uh.x = split_pack_hi(f[0], f[1], ul.x);
                uh.y = split_pack_hi(f[2], f[3], ul.y);
                int off = n * LDA + k4 * 4;
                *(uint2*)&BhA[off] = uh;
                *(uint2*)&BlA[off] = ul;
            }
        }
        __syncthreads();                        // h tiles (and Wc) complete

        // ---- phase 2: h2 = relu(h @ Wb + bb) ----
#pragma unroll
        for (int i = 0; i < 2; i++)
#pragma unroll
            for (int j = 0; j < 4; j++)
#pragma unroll
                for (int q = 0; q < 4; q++) acc[i][j][q] = 0.f;

        gemm_mainloop<4>(sAh, sAl, smem_u32(BhB), smem_u32(BlB), wm, wn, lane, acc);

        if (!DO_CLS) {
#pragma unroll
            for (int mi = 0; mi < 2; mi++) {
                int r_lo = m0 + wm + mi * 16 + (lane >> 2);
                int r_hi = r_lo + 8;
#pragma unroll
                for (int ni = 0; ni < 4; ni++) {
                    int col = wn + ni * 8 + (lane & 3) * 2;
                    float v00 = fmaxf(acc[mi][ni][0] + sbB[col], 0.f);
                    float v01 = fmaxf(acc[mi][ni][1] + sbB[col + 1], 0.f);
                    float v10 = fmaxf(acc[mi][ni][2] + sbB[col], 0.f);
                    float v11 = fmaxf(acc[mi][ni][3] + sbB[col + 1], 0.f);
                    if (r_lo < N_NODES) *(float2*)&C[r_lo * 128 + col] = make_float2(v00, v01);
                    if (r_hi < N_NODES) *(float2*)&C[r_hi * 128 + col] = make_float2(v10, v11);
                }
            }
        } else {
            // ---- phase 3: out = h2 @ Wc + bc (h2 stays in smem) ----
            __syncthreads();                    // mainloop2 reads of A done
#pragma unroll
            for (int mi = 0; mi < 2; mi++) {
                int r_lo = wm + mi * 16 + (lane >> 2);
                int r_hi = r_lo + 8;
#pragma unroll
                for (int ni = 0; ni < 4; ni++) {
                    int col = wn + ni * 8 + (lane & 3) * 2;
                    float v00 = fmaxf(acc[mi][ni][0] + sbB[col], 0.f);
                    float v01 = fmaxf(acc[mi][ni][1] + sbB[col + 1], 0.f);
                    float v10 = fmaxf(acc[mi][ni][2] + sbB[col], 0.f);
                    float v11 = fmaxf(acc[mi][ni][3] + sbB[col + 1], 0.f);
                    uint32_t lo;
                    *(uint32_t*)&Ah[r_lo * LDA + col] = split_pack_hi(v00, v01, lo);
                    *(uint32_t*)&Al[r_lo * LDA + col] = lo;
                    *(uint32_t*)&Ah[r_hi * LDA + col] = split_pack_hi(v10, v11, lo);
                    *(uint32_t*)&Al[r_hi * LDA + col] = lo;
                }
            }
            __syncthreads();                    // h2 tiles complete

            float acc2[2][2][4];
#pragma unroll
            for (int i = 0; i < 2; i++)
#pragma unroll
                for (int j = 0; j < 2; j++)
#pragma unroll
                    for (int q = 0; q < 4; q++) acc2[i][j][q] = 0.f;

            const int wnc = (wid & 3) * 16;
            gemm_mainloop<2>(sAh, sAl, smem_u32(BhA), smem_u32(BlA), wm, wnc, lane, acc2);

#pragma unroll
            for (int mi = 0; mi < 2; mi++) {
                int r_lo = m0 + wm + mi * 16 + (lane >> 2);
                int r_hi = r_lo + 8;
#pragma unroll
                for (int ni = 0; ni < 2; ni++) {
                    int col = wnc + ni * 8 + (lane & 3) * 2;
                    float v00 = acc2[mi][ni][0] + sbC[col];
                    float v01 = acc2[mi][ni][1] + sbC[col + 1];
                    float v10 = acc2[mi][ni][2] + sbC[col];
                    float v11 = acc2[mi][ni][3] + sbC[col + 1];
                    if (r_lo < N_NODES) {
                        if (col < NCLS)     Cout[r_lo * NCLS + col]     = v00;
                        if (col + 1 < NCLS) Cout[r_lo * NCLS + col + 1] = v01;
                    }
                    if (r_hi < N_NODES) {
                        if (col < NCLS)     Cout[r_hi * NCLS + col]     = v10;
                        if (col + 1 < NCLS) Cout[r_hi * NCLS + col + 1] = v11;
                    }
                }
            }
        }
    }
}

// ============================ launch ============================
extern "C" void kernel_launch(void* const* d_in, const int* in_sizes, int n_in,
                              void* d_out, int out_size) {
    const float4* x  = (const float4*)d_in[0];
    const int*    ei = (const int*)d_in[1];
    const float* w1a = (const float*)d_in[2];
    const float* b1a = (const float*)d_in[3];
    const float* w1b = (const float*)d_in[4];
    const float* b1b = (const float*)d_in[5];
    const float* w2a = (const float*)d_in[6];
    const float* b2a = (const float*)d_in[7];
    const float* w2b = (const float*)d_in[8];
    const float* b2b = (const float*)d_in[9];
    const float* wlin = (const float*)d_in[10];
    const float* blin = (const float*)d_in[11];
    float* out = (float*)d_out;

    const int SMEM_M = 2048 + 6 * (128 * LDA * 2);   // 210944
    cudaFuncSetAttribute((const void*)k_mlp<0>, cudaFuncAttributeMaxDynamicSharedMemorySize, SMEM_M);
    cudaFuncSetAttribute((const void*)k_mlp<1>, cudaFuncAttributeMaxDynamicSharedMemorySize, SMEM_M);

    const int EDGE_BLOCKS = (N_EDGES + 255) / 256;       // 2500
    const int NODE_BLOCKS = (N_NODES + 255) / 256;       // 157
    const int AGG_BLOCKS  = (N_NODES * 32 + 255) / 256;  // 5000

    // bucket CSR build (2 kernels)
    k_init<<<NODE_BLOCKS, 256>>>(ei);
    k_scatter<<<EDGE_BLOCKS, 256>>>(ei);

    // layer 1: agg (x -> b0), fused persistent MLP (b0 -> b1)
    k_agg<<<AGG_BLOCKS, 256>>>(x, -1, 0);
    k_mlp<0><<<MLP_GRID, 512, SMEM_M>>>(0, w1a, b1a, w1b, b1b, 1,
                                        nullptr, nullptr, nullptr);

    // layer 2 + classifier: agg (b1 -> b0), fused MLP+cls (b0 -> out)
    k_agg<<<AGG_BLOCKS, 256>>>(nullptr, 1, 0);
    k_mlp<1><<<MLP_GRID, 512, SMEM_M>>>(0, w2a, b2a, w2b, b2b, 2,
                                        wlin, blin, out);
}

// round 15
// speedup vs baseline: 1.0675x; 1.0117x over previous
#include <cuda_runtime.h>
#include <cuda_bf16.h>
#include <cstdint>

#define N_NODES 40000
#define N_EDGES 640000
#define CH 128
#define NCLS 40
#define CAP 96          // bucket capacity per node (mean degree 16, Poisson tail ~0)

// ---- scratch (static __device__ arrays; no allocations allowed) ----
__device__ float4 g_b0[N_NODES * 32];
__device__ float4 g_b1[N_NODES * 32];
__device__ float4 g_b2[N_NODES * 32];
__device__ int    g_cursor[N_NODES];
__device__ int    g_bsrcs[N_NODES * CAP];   // bucketed src lists
__device__ int    g_is64;

__device__ __forceinline__ float4* pick_buf(int s) {
    return (s == 0) ? g_b0 : (s == 1) ? g_b1 : g_b2;
}

__device__ __forceinline__ uint32_t smem_u32(const void* p) {
    uint32_t a;
    asm("{ .reg .u64 t; cvta.to.shared.u64 t, %1; cvt.u32.u64 %0, t; }" : "=r"(a) : "l"(p));
    return a;
}

// ---- width-aware edge-index load (dtype detected in k_init) ----
__device__ __forceinline__ int ld_idx(const int* __restrict__ e, int pos) {
    int v = g_is64 ? e[2 * pos] : e[pos];
    return min(max(v, 0), N_NODES - 1);
}

// ================== bucket CSR build (2 kernels) ==================
__global__ void k_init(const int* __restrict__ e) {
    int i = blockIdx.x * blockDim.x + threadIdx.x;
    if (i < N_NODES) g_cursor[i] = 0;
    if (i == 0) {
        int nz = 0;
        for (int j = 1; j < 256; j += 2) nz |= e[j];
        g_is64 = (nz == 0) ? 1 : 0;
    }
}
__global__ void k_scatter(const int* __restrict__ e) {
    int i = blockIdx.x * blockDim.x + threadIdx.x;
    if (i < N_EDGES) {
        int d = ld_idx(e, N_EDGES + i);
        int p = atomicAdd(&g_cursor[d], 1);
        if (p < CAP) g_bsrcs[d * CAP + p] = ld_idx(e, i);
    }
}

// ========== aggregation: dst[n] = X[n] + sum_{e: dst=n} X[src[e]] ==========
// warp-per-node, 4-way ILP on the random row gathers.
__global__ void k_agg(const float4* __restrict__ Xext, int src_sel, int dst_sel) {
    int warp = (blockIdx.x * blockDim.x + threadIdx.x) >> 5;
    int lane = threadIdx.x & 31;
    if (warp >= N_NODES) return;
    const float4* X4 = (src_sel < 0) ? Xext : pick_buf(src_sel);
    float4 a0 = X4[warp * 32 + lane];
    float4 a1 = make_float4(0.f, 0.f, 0.f, 0.f);
    float4 a2 = a1, a3 = a1;
    int n  = min(g_cursor[warp], CAP);
    const int* srcs = &g_bsrcs[warp * CAP];
    int j = 0;
    for (; j + 3 < n; j += 4) {
        int sA = srcs[j],     sB = srcs[j + 1];
        int sC = srcs[j + 2], sD = srcs[j + 3];
        float4 vA = X4[sA * 32 + lane], vB = X4[sB * 32 + lane];
        float4 vC = X4[sC * 32 + lane], vD = X4[sD * 32 + lane];
        a0.x += vA.x; a0.y += vA.y; a0.z += vA.z; a0.w += vA.w;
        a1.x += vB.x; a1.y += vB.y; a1.z += vB.z; a1.w += vB.w;
        a2.x += vC.x; a2.y += vC.y; a2.z += vC.z; a2.w += vC.w;
        a3.x += vD.x; a3.y += vD.y; a3.z += vD.z; a3.w += vD.w;
    }
    for (; j < n; j++) {
        int s = srcs[j];
        float4 v = X4[s * 32 + lane];
        a0.x += v.x; a0.y += v.y; a0.z += v.z; a0.w += v.w;
    }
    a0.x += a1.x + a2.x + a3.x; a0.y += a1.y + a2.y + a3.y;
    a0.z += a1.z + a2.z + a3.z; a0.w += a1.w + a2.w + a3.w;
    pick_buf(dst_sel)[warp * 32 + lane] = a0;
}

// ======================= MMA primitives =======================
#define LDA 136   // bf16 per smem row (128 + 8 pad) -> 272B stride (17x16B: conflict-free)

__device__ __forceinline__ uint32_t pack_bf2(__nv_bfloat16 a, __nv_bfloat16 b) {
    __nv_bfloat162 p(a, b);
    return *(uint32_t*)&p;
}
__device__ __forceinline__ uint32_t split_pack_hi(float a, float b,
                                                  uint32_t& lo_out) {
    __nv_bfloat16 ha = __float2bfloat16(a), hb = __float2bfloat16(b);
    lo_out = pack_bf2(__float2bfloat16(a - __bfloat162float(ha)),
                      __float2bfloat16(b - __bfloat162float(hb)));
    return pack_bf2(ha, hb);
}
__device__ __forceinline__ void ldm_x4(uint32_t* r, uint32_t addr) {
    asm volatile("ldmatrix.sync.aligned.m8n8.x4.shared.b16 {%0,%1,%2,%3}, [%4];"
        : "=r"(r[0]), "=r"(r[1]), "=r"(r[2]), "=r"(r[3]) : "r"(addr));
}
__device__ __forceinline__ void mma_bf16(float* c, const uint32_t* a, const uint32_t* b) {
    asm volatile(
        "mma.sync.aligned.m16n8k16.row.col.f32.bf16.bf16.f32 "
        "{%0,%1,%2,%3}, {%4,%5,%6,%7}, {%8,%9}, {%0,%1,%2,%3};"
        : "+f"(c[0]), "+f"(c[1]), "+f"(c[2]), "+f"(c[3])
        : "r"(a[0]), "r"(a[1]), "r"(a[2]), "r"(a[3]), "r"(b[0]), "r"(b[1]));
}

// 128xBNx128 3-product mainloop; B fragments loaded pairwise via ldmatrix.x4.
// MMA terms issued term-outermost: same-accumulator reuse distance = 2*NI
// (was 1 -> back-to-back HMMA RAW chains).
template<int NI>
__device__ __forceinline__ void gemm_mainloop(
    uint32_t sAh, uint32_t sAl, uint32_t sBh, uint32_t sBl,
    int wm, int wn, int lane, float acc[2][NI][4]) {
    const int la  = lane & 15;
    const int lka = (lane >> 4) * 8;
    const int lbx = ((lane >> 4) & 1) * 8 + (lane & 7);   // row for paired-B x4
    const int lkb = ((lane >> 3) & 1) * 8;
#pragma unroll
    for (int kb = 0; kb < 8; kb++) {
        uint32_t ah[2][4], al[2][4], bh[NI][2], bl[NI][2];
#pragma unroll
        for (int mi = 0; mi < 2; mi++) {
            uint32_t off = ((wm + mi * 16 + la) * LDA + kb * 16 + lka) * 2;
            ldm_x4(ah[mi], sAh + off);
            ldm_x4(al[mi], sAl + off);
        }
#pragma unroll
        for (int np = 0; np < NI; np += 2) {   // 2 n-frags per x4
            uint32_t off = ((wn + np * 8 + lbx) * LDA + kb * 16 + lkb) * 2;
            uint32_t t4[4];
            ldm_x4(t4, sBh + off);
            bh[np][0] = t4[0]; bh[np][1] = t4[1];
            bh[np + 1][0] = t4[2]; bh[np + 1][1] = t4[3];
            ldm_x4(t4, sBl + off);
            bl[np][0] = t4[0]; bl[np][1] = t4[1];
            bl[np + 1][0] = t4[2]; bl[np + 1][1] = t4[3];
        }
        // term 1: Ah*Bh
#pragma unroll
        for (int mi = 0; mi < 2; mi++)
#pragma unroll
            for (int ni = 0; ni < NI; ni++)
                mma_bf16(acc[mi][ni], ah[mi], bh[ni]);
        // term 2: Ah*Bl
#pragma unroll
        for (int mi = 0; mi < 2; mi++)
#pragma unroll
            for (int ni = 0; ni < NI; ni++)
                mma_bf16(acc[mi][ni], ah[mi], bl[ni]);
        // term 3: Al*Bh
#pragma unroll
        for (int mi = 0; mi < 2; mi++)
#pragma unroll
            for (int ni = 0; ni < NI; ni++)
                mma_bf16(acc[mi][ni], al[mi], bh[ni]);
    }
}

// fp32 weight [128][128] (k-major) -> [n][k] bf16 hi/lo smem tiles
__device__ __forceinline__ void load_weights(
    const float* __restrict__ W, __nv_bfloat16* Bh, __nv_bfloat16* Bl, int tid) {
#pragma unroll
    for (int it = 0; it < 8; it++) {
        int idx = tid + it * 512;
        int n  = idx & 127;
        int k4 = idx >> 7;
        float f[4];
#pragma unroll
        for (int j = 0; j < 4; j++) f[j] = W[(k4 * 4 + j) * 128 + n];
        uint2 uh, ul;
        uh.x = split_pack_hi(f[0], f[1], ul.x);
        uh.y = split_pack_hi(f[2], f[3], ul.y);
        int off = n * LDA + k4 * 4;
        *(uint2*)&Bh[off] = uh;
        *(uint2*)&Bl[off] = ul;
    }
}

#define GEMM_BLOCKS ((N_NODES + 127) / 128)   // 313
#define MLP_GRID 148                          // persistent: one CTA per SM

// ========== fused MLP (persistent), optionally + classifier ==========
// DO_CLS=0: dst = relu( relu(A@Wa+ba) @ Wb + bb )   -> pick_buf(dst_sel)
// DO_CLS=1: out = ( relu( relu(A@Wa+ba) @ Wb + bb ) ) @ Wc + bc  -> Cout [N,NCLS]
//   h2 never touches global; Wc lives in the Wa tile slots after mainloop1.
template<int DO_CLS>
__global__ __launch_bounds__(512, 1)
void k_mlp(int src_sel,
           const float* __restrict__ Wa, const float* __restrict__ ba,
           const float* __restrict__ Wb, const float* __restrict__ bb,
           int dst_sel,
           const float* __restrict__ Wc, const float* __restrict__ bc,
           float* __restrict__ Cout) {
    extern __shared__ char sm[];
    constexpr int SZ = 128 * LDA * 2;          // 34816 B
    const int OFF_AH = 2048,        OFF_AL = OFF_AH + SZ;
    const int OFF_BHA = OFF_AL + SZ,  OFF_BLA = OFF_BHA + SZ;
    const int OFF_BHB = OFF_BLA + SZ, OFF_BLB = OFF_BHB + SZ;
    float* sbA = (float*)sm;                    // [0,512)
    float* sbB = (float*)(sm + 512);            // [512,1024)
    float* sbC = (float*)(sm + 1024);           // [1024,1280) 64 floats
    __nv_bfloat16* Ah  = (__nv_bfloat16*)(sm + OFF_AH);
    __nv_bfloat16* Al  = (__nv_bfloat16*)(sm + OFF_AL);
    __nv_bfloat16* BhA = (__nv_bfloat16*)(sm + OFF_BHA);
    __nv_bfloat16* BlA = (__nv_bfloat16*)(sm + OFF_BLA);
    __nv_bfloat16* BhB = (__nv_bfloat16*)(sm + OFF_BHB);
    __nv_bfloat16* BlB = (__nv_bfloat16*)(sm + OFF_BLB);

    const int tid = threadIdx.x, lane = tid & 31, wid = tid >> 5;
    if (tid < 128) { sbA[tid] = ba[tid]; sbB[tid] = bb[tid]; }
    if (DO_CLS && tid < 64) sbC[tid] = (tid < NCLS) ? bc[tid] : 0.f;
    if (!DO_CLS) load_weights(Wa, BhA, BlA, tid);   // CLS path reloads Wa per tile
    load_weights(Wb, BhB, BlB, tid);

    const int wm = (wid >> 2) * 32;
    const int wn = (wid & 3) * 32;
    const uint32_t sAh = smem_u32(Ah), sAl = smem_u32(Al);
    const float4* A4 = pick_buf(src_sel);
    float* C = (float*)pick_buf(dst_sel);

    for (int t = blockIdx.x; t < GEMM_BLOCKS; t += MLP_GRID) {
        const int m0 = t * 128;
        __syncthreads();   // prev iter's last mainloop reads done; iter0: weights visible

        if (DO_CLS) load_weights(Wa, BhA, BlA, tid);   // Wa slot was Wc last iter

        // ---- A tile: fp32 -> hi/lo bf16 split ----
#pragma unroll
        for (int it = 0; it < 8; it++) {
            int idx = tid + it * 512;
            int r  = idx >> 5;
            int kk = idx & 31;
            int row = m0 + r;
            float4 v = make_float4(0.f, 0.f, 0.f, 0.f);
            if (row < N_NODES) v = A4[row * 32 + kk];
            uint2 uh, ul;
            uh.x = split_pack_hi(v.x, v.y, ul.x);
            uh.y = split_pack_hi(v.z, v.w, ul.y);
            int off = r * LDA + kk * 4;
            *(uint2*)&Ah[off] = uh;
            *(uint2*)&Al[off] = ul;
        }
        __syncthreads();

        // ---- phase 1: h = relu(A @ Wa + ba) ----
        float acc[2][4][4];
#pragma unroll
        for (int i = 0; i < 2; i++)
#pragma unroll
            for (int j = 0; j < 4; j++)
#pragma unroll
                for (int q = 0; q < 4; q++) acc[i][j][q] = 0.f;

        gemm_mainloop<4>(sAh, sAl, smem_u32(BhA), smem_u32(BlA), wm, wn, lane, acc);
        __syncthreads();                        // all reads of A (and Wa) done

        // repack h into A tiles; CLS: also stage Wc into the free Wa slots
#pragma unroll
        for (int mi = 0; mi < 2; mi++) {
            int r_lo = wm + mi * 16 + (lane >> 2);
            int r_hi = r_lo + 8;
#pragma unroll
            for (int ni = 0; ni < 4; ni++) {
                int col = wn + ni * 8 + (lane & 3) * 2;
                float v00 = fmaxf(acc[mi][ni][0] + sbA[col], 0.f);
                float v01 = fmaxf(acc[mi][ni][1] + sbA[col + 1], 0.f);
                float v10 = fmaxf(acc[mi][ni][2] + sbA[col], 0.f);
                float v11 = fmaxf(acc[mi][ni][3] + sbA[col + 1], 0.f);
                uint32_t lo;
                *(uint32_t*)&Ah[r_lo * LDA + col] = split_pack_hi(v00, v01, lo);
                *(uint32_t*)&Al[r_lo * LDA + col] = lo;
                *(uint32_t*)&Ah[r_hi * LDA + col] = split_pack_hi(v10, v11, lo);
                *(uint32_t*)&Al[r_hi * LDA + col] = lo;
            }
        }
        if (DO_CLS) {
#pragma unroll
            for (int it = 0; it < 4; it++) {
                int idx = tid + it * 512;      // 2048 (n,k4) pairs: 64 x 32
                int n  = idx & 63;
                int k4 = idx >> 6;
                float f[4];
#pragma unroll
                for (int j = 0; j < 4; j++)
                    f[j] = (n < NCLS) ? Wc[(k4 * 4 + j) * NCLS + n] : 0.f;
                uint2 uh, ul;
                uh.x = split_pack_hi(f[0], f[1], ul.x);
                uh.y = split_pack_hi(f[2], f[3], ul.y);
                int off = n * LDA + k4 * 4;
                *(uint2*)&BhA[off] = uh;
                *(uint2*)&BlA[off] = ul;
            }
        }
        __syncthreads();                        // h tiles (and Wc) complete

        // ---- phase 2: h2 = relu(h @ Wb + bb) ----
#pragma unroll
        for (int i = 0; i < 2; i++)
#pragma unroll
            for (int j = 0; j < 4; j++)
#pragma unroll
                for (int q = 0; q < 4; q++) acc[i][j][q] = 0.f;

        gemm_mainloop<4>(sAh, sAl, smem_u32(BhB), smem_u32(BlB), wm, wn, lane, acc);

        if (!DO_CLS) {
#pragma unroll
            for (int mi = 0; mi < 2; mi++) {
                int r_lo = m0 + wm + mi * 16 + (lane >> 2);
                int r_hi = r_lo + 8;
#pragma unroll
                for (int ni = 0; ni < 4; ni++) {
                    int col = wn + ni * 8 + (lane & 3) * 2;
                    float v00 = fmaxf(acc[mi][ni][0] + sbB[col], 0.f);
                    float v01 = fmaxf(acc[mi][ni][1] + sbB[col + 1], 0.f);
                    float v10 = fmaxf(acc[mi][ni][2] + sbB[col], 0.f);
                    float v11 = fmaxf(acc[mi][ni][3] + sbB[col + 1], 0.f);
                    if (r_lo < N_NODES) *(float2*)&C[r_lo * 128 + col] = make_float2(v00, v01);
                    if (r_hi < N_NODES) *(float2*)&C[r_hi * 128 + col] = make_float2(v10, v11);
                }
            }
        } else {
            // ---- phase 3: out = h2 @ Wc + bc (h2 stays in smem) ----
            __syncthreads();                    // mainloop2 reads of A done
#pragma unroll
            for (int mi = 0; mi < 2; mi++) {
                int r_lo = wm + mi * 16 + (lane >> 2);
                int r_hi = r_lo + 8;
#pragma unroll
                for (int ni = 0; ni < 4; ni++) {
                    int col = wn + ni * 8 + (lane & 3) * 2;
                    float v00 = fmaxf(acc[mi][ni][0] + sbB[col], 0.f);
                    float v01 = fmaxf(acc[mi][ni][1] + sbB[col + 1], 0.f);
                    float v10 = fmaxf(acc[mi][ni][2] + sbB[col], 0.f);
                    float v11 = fmaxf(acc[mi][ni][3] + sbB[col + 1], 0.f);
                    uint32_t lo;
                    *(uint32_t*)&Ah[r_lo * LDA + col] = split_pack_hi(v00, v01, lo);
                    *(uint32_t*)&Al[r_lo * LDA + col] = lo;
                    *(uint32_t*)&Ah[r_hi * LDA + col] = split_pack_hi(v10, v11, lo);
                    *(uint32_t*)&Al[r_hi * LDA + col] = lo;
                }
            }
            __syncthreads();                    // h2 tiles complete

            float acc2[2][2][4];
#pragma unroll
            for (int i = 0; i < 2; i++)
#pragma unroll
                for (int j = 0; j < 2; j++)
#pragma unroll
                    for (int q = 0; q < 4; q++) acc2[i][j][q] = 0.f;

            const int wnc = (wid & 3) * 16;
            gemm_mainloop<2>(sAh, sAl, smem_u32(BhA), smem_u32(BlA), wm, wnc, lane, acc2);

#pragma unroll
            for (int mi = 0; mi < 2; mi++) {
                int r_lo = m0 + wm + mi * 16 + (lane >> 2);
                int r_hi = r_lo + 8;
#pragma unroll
                for (int ni = 0; ni < 2; ni++) {
                    int col = wnc + ni * 8 + (lane & 3) * 2;
                    float v00 = acc2[mi][ni][0] + sbC[col];
                    float v01 = acc2[mi][ni][1] + sbC[col + 1];
                    float v10 = acc2[mi][ni][2] + sbC[col];
                    float v11 = acc2[mi][ni][3] + sbC[col + 1];
                    if (r_lo < N_NODES) {
                        if (col < NCLS)     Cout[r_lo * NCLS + col]     = v00;
                        if (col + 1 < NCLS) Cout[r_lo * NCLS + col + 1] = v01;
                    }
                    if (r_hi < N_NODES) {
                        if (col < NCLS)     Cout[r_hi * NCLS + col]     = v10;
                        if (col + 1 < NCLS) Cout[r_hi * NCLS + col + 1] = v11;
                    }
                }
            }
        }
    }
}

// ============================ launch ============================
extern "C" void kernel_launch(void* const* d_in, const int* in_sizes, int n_in,
                              void* d_out, int out_size) {
    const float4* x  = (const float4*)d_in[0];
    const int*    ei = (const int*)d_in[1];
    const float* w1a = (const float*)d_in[2];
    const float* b1a = (const float*)d_in[3];
    const float* w1b = (const float*)d_in[4];
    const float* b1b = (const float*)d_in[5];
    const float* w2a = (const float*)d_in[6];
    const float* b2a = (const float*)d_in[7];
    const float* w2b = (const float*)d_in[8];
    const float* b2b = (const float*)d_in[9];
    const float* wlin = (const float*)d_in[10];
    const float* blin = (const float*)d_in[11];
    float* out = (float*)d_out;

    const int SMEM_M = 2048 + 6 * (128 * LDA * 2);   // 210944
    cudaFuncSetAttribute((const void*)k_mlp<0>, cudaFuncAttributeMaxDynamicSharedMemorySize, SMEM_M);
    cudaFuncSetAttribute((const void*)k_mlp<1>, cudaFuncAttributeMaxDynamicSharedMemorySize, SMEM_M);

    const int EDGE_BLOCKS = (N_EDGES + 255) / 256;       // 2500
    const int NODE_BLOCKS = (N_NODES + 255) / 256;       // 157
    const int AGG_BLOCKS  = (N_NODES * 32 + 255) / 256;  // 5000

    // bucket CSR build (2 kernels)
    k_init<<<NODE_BLOCKS, 256>>>(ei);
    k_scatter<<<EDGE_BLOCKS, 256>>>(ei);

    // layer 1: agg (x -> b0), fused persistent MLP (b0 -> b1)
    k_agg<<<AGG_BLOCKS, 256>>>(x, -1, 0);
    k_mlp<0><<<MLP_GRID, 512, SMEM_M>>>(0, w1a, b1a, w1b, b1b, 1,
                                        nullptr, nullptr, nullptr);

    // layer 2 + classifier: agg (b1 -> b0), fused MLP+cls (b0 -> out)
    k_agg<<<AGG_BLOCKS, 256>>>(nullptr, 1, 0);
    k_mlp<1><<<MLP_GRID, 512, SMEM_M>>>(0, w2a, b2a, w2b, b2b, 2,
                                        wlin, blin, out);
}